// round 7
// baseline (speedup 1.0000x reference)
#include <cuda_runtime.h>
#include <cuda_fp16.h>
#include <cstdint>

// TALayer = 9-tap conv, tap offsets d_j = 16*(j/3)+(j%3)-17.
// GEMM form: D[o,t] = sum_k W[o,k]*X[k,t], k=(j,c), K=576.
// fp16 mma.sync m16n8k16 (fp32 accum). Split-o: CTA = 32 o x 128 t,
// 3 CTAs/SM x 256 thr (24 warps/SM), warp tile = 16o x 32t.

#define T_LEN  65536
#define NO     64
#define NC     64
#define T_TILE 128
#define HALO   17
#define XROWS  (T_TILE + 2*HALO)   // 162
#define XSTW   36                  // uint32 words per x row (stride ≡ 4 mod 32)
#define NCHUNK 36                  // K=576 / 16
#define GRID   444                 // 3 CTAs/SM * 148
#define NTILES 8192                // 2 oh * 8 b * 512 ttiles

// smem byte offsets (per CTA)
#define WFOFF   0
#define WFBYTES (NCHUNK*2*32*16)        // 36864: [chunk][mt(2)][lane]{a0..a3}
#define XSOFF   WFBYTES
#define XSBYTES (XROWS*XSTW*4)          // 23328
#define BOFF    (XSOFF + XSBYTES)       // 60192
#define SMTOT   (BOFF + 256)            // 60448

// W fragments, exact m16n8k16 f16 A-frag layout: [oh][chunk][mt][lane]{4 regs}
__device__ uint32_t g_wfrag[2*NCHUNK*2*32*4];

__device__ __forceinline__ uint32_t packh2(float lo, float hi) {
    __half2 h = __floats2half2_rn(lo, hi);
    return *(uint32_t*)&h;
}

__global__ void prep_w(const float* __restrict__ w) {
    int tid = blockIdx.x * blockDim.x + threadIdx.x;
    if (tid >= 2 * NCHUNK * 2 * 32) return;
    int oh   = tid / (NCHUNK * 64);
    int rem  = tid % (NCHUNK * 64);
    int q    = rem >> 6;
    int mt   = (rem >> 5) & 1;
    int lane = rem & 31;
    int j = q >> 2, cq = q & 3;
    int o0 = oh * 32 + mt * 16 + (lane >> 2);
    int c0 = cq * 16 + (lane & 3) * 2;
    uint4 u;
    u.x = packh2(w[o0*576 + c0*9 + j],        w[o0*576 + (c0+1)*9 + j]);
    u.y = packh2(w[(o0+8)*576 + c0*9 + j],    w[(o0+8)*576 + (c0+1)*9 + j]);
    u.z = packh2(w[o0*576 + (c0+8)*9 + j],    w[o0*576 + (c0+9)*9 + j]);
    u.w = packh2(w[(o0+8)*576 + (c0+8)*9 + j],w[(o0+8)*576 + (c0+9)*9 + j]);
    ((uint4*)g_wfrag)[tid] = u;
}

extern __shared__ char sm[];

__global__ __launch_bounds__(256, 3) void taconv_mma(
    const float* __restrict__ x, const float* __restrict__ bias,
    float* __restrict__ out)
{
    const int tid  = threadIdx.x;
    const int wid  = tid >> 5;
    const int lane = tid & 31;
    const int og   = wid & 1;        // mtile within this CTA's 32-o half
    const int tg   = wid >> 1;       // t-group: 32 time steps (4 groups)

    // oh is fixed per CTA for the whole persistent loop (tile & 1 pattern with
    // stride GRID=444 keeps parity of blockIdx.x), so derive it once per tile.

    const int wrow = tg * 32 + (lane >> 2);   // B-frag t-row base (pre-shift)

    int prev_oh = -1;

    for (int tile = blockIdx.x; tile < NTILES; tile += GRID) {
        const int oh = tile & 1;
        const int tt = (tile >> 1) & 511;
        const int b  = tile >> 10;
        const int t0 = tt << 7;

        __syncthreads();   // xs/W safe to overwrite

        // ---- stage W fragments for this oh (only when oh changes) ----
        if (oh != prev_oh) {
            const uint4* gw = (const uint4*)g_wfrag + oh * (NCHUNK * 64);
            uint4* sw = (uint4*)(sm + WFOFF);
            for (int i = tid; i < NCHUNK * 64; i += 256) sw[i] = gw[i];
            if (tid < 32) ((float*)(sm + BOFF))[tid] = bias[oh * 32 + tid];
            prev_oh = oh;
        }

        // ---- x tile -> smem as fp16, t-major: xs[i][c] ----
        const float* xb = x + (size_t)b * NC * T_LEN;
        __half* xsh = (__half*)(sm + XSOFF);
#pragma unroll 6
        for (int it = 0; it < 41; ++it) {
            int idx = it * 256 + tid;              // idx = c*162 + i
            if (idx < NC * XROWS) {
                int c = idx / XROWS, i = idx - c * XROWS;
                int g = t0 - HALO + i;
                float v = (g >= 0 && g < T_LEN)
                        ? __ldg(xb + (size_t)c * T_LEN + g) : 0.0f;
                xsh[i * (2 * XSTW) + c] = __float2half_rn(v);
            }
        }
        __syncthreads();

        // ---- mainloop: 36 K-chunks (k=16), 4 mma each ----
        float acc[4][4];
#pragma unroll
        for (int n = 0; n < 4; ++n)
#pragma unroll
            for (int r = 0; r < 4; ++r) acc[n][r] = 0.0f;

        const uint4* wf_base = (const uint4*)(sm + WFOFF);
        const uint32_t* xs = (const uint32_t*)(sm + XSOFF);

#pragma unroll
        for (int j = 0; j < 9; ++j) {
            const int offj = 16 * (j / 3) + (j % 3);   // d_j + HALO
#pragma unroll
            for (int cq = 0; cq < 4; ++cq) {
                const int q = j * 4 + cq;
                uint4 wf = wf_base[(q * 2 + og) * 32 + lane];

                uint32_t bb[4][2];
                const uint32_t* bp =
                    xs + (wrow + offj) * XSTW + cq * 8 + (lane & 3);
#pragma unroll
                for (int nt = 0; nt < 4; ++nt) {
                    bb[nt][0] = bp[nt * 8 * XSTW];
                    bb[nt][1] = bp[nt * 8 * XSTW + 4];
                }
#pragma unroll
                for (int nt = 0; nt < 4; ++nt)
                    asm volatile(
                        "mma.sync.aligned.m16n8k16.row.col.f32.f16.f16.f32 "
                        "{%0,%1,%2,%3}, {%4,%5,%6,%7}, {%8,%9}, {%0,%1,%2,%3};"
                        : "+f"(acc[nt][0]), "+f"(acc[nt][1]),
                          "+f"(acc[nt][2]), "+f"(acc[nt][3])
                        : "r"(wf.x), "r"(wf.y), "r"(wf.z), "r"(wf.w),
                          "r"(bb[nt][0]), "r"(bb[nt][1]));
            }
        }

        // ---- epilogue: +bias, STG.64 per C-fragment pair ----
        int oA = og * 16 + (lane >> 2);          // within this CTA's half
        float bv0 = ((float*)(sm + BOFF))[oA];
        float bv1 = ((float*)(sm + BOFF))[oA + 8];
        float* ob = out + ((size_t)b * NO + oh * 32) * T_LEN
                        + t0 + tg * 32 + 2 * (lane & 3);
#pragma unroll
        for (int nt = 0; nt < 4; ++nt) {
            float2 v0 = make_float2(acc[nt][0] + bv0, acc[nt][1] + bv0);
            float2 v1 = make_float2(acc[nt][2] + bv1, acc[nt][3] + bv1);
            *(float2*)(ob + (size_t)oA * T_LEN + nt * 8) = v0;
            *(float2*)(ob + (size_t)(oA + 8) * T_LEN + nt * 8) = v1;
        }
    }
}

extern "C" void kernel_launch(void* const* d_in, const int* in_sizes, int n_in,
                              void* d_out, int out_size) {
    const float* x    = (const float*)d_in[0];
    const float* w    = (const float*)d_in[1];
    const float* bias = (const float*)d_in[2];
    float* out = (float*)d_out;

    prep_w<<<(2 * NCHUNK * 64 + 255) / 256, 256>>>(w);

    cudaFuncSetAttribute(taconv_mma,
                         cudaFuncAttributeMaxDynamicSharedMemorySize, SMTOT);
    taconv_mma<<<GRID, 256, SMTOT>>>(x, bias, out);
}